// round 12
// baseline (speedup 1.0000x reference)
#include <cuda_runtime.h>
#include <cuda_bf16.h>
#include <cstdint>

// MendGraph: fill_feats = [x; gen_feats], fill_edges = [edge_index | synthetic],
// edge_mask = [ones(E) | k < clip(round(pred_missing),0,P)].
//
// Output: 79,950,000 f32, flat concat (all cast to f32):
//   [0, NFx) x | [NFx, NFx+NFg) gen_feats | [B, B+M) src | [B+M, B+2M) dst | [B+2M, B+3M) mask
// B = NFx+NFg, M = E + N*P.  edge_index input is int32.
//
// Persistent variant of the session-best config: fixed grid (148 SMs x 8 CTAs),
// each thread grid-strides over float4 groups with .cs loads+stores (measured
// best policy). Edge/mask generation runs AFTER the copy loop on the first
// M/4 threads, i.e. in tail slack.

__global__ void fused_kernel(const float4* __restrict__ x,
                             const float4* __restrict__ g,
                             const int*    __restrict__ ei,   // [2, E] int32
                             const float*  __restrict__ pm,   // [N]
                             float4* __restrict__ out,
                             int nx4, int total4,
                             int e_base4, int edges4,
                             int E, int M, int N, int P)
{
    const int tid    = blockIdx.x * blockDim.x + threadIdx.x;
    const int stride = gridDim.x * blockDim.x;

    // ---- streaming copy: grid-stride over float4 groups ----
    for (int k = tid; k < total4; k += stride) {
        float4 v = (k < nx4) ? __ldcs(&x[k]) : __ldcs(&g[k - nx4]);
        __stcs(&out[k], v);
    }

    // ---- edges + mask: first edges4 threads, after their copy loop ----
    if (tid < edges4) {
        int j0 = tid * 4;
        float4 s4, d4, m4;
        if (j0 + 3 < E) {                    // E is 4-aligned: no straddle
            s4 = make_float4((float)ei[j0],   (float)ei[j0+1],
                             (float)ei[j0+2], (float)ei[j0+3]);
            d4 = make_float4((float)ei[E+j0],   (float)ei[E+j0+1],
                             (float)ei[E+j0+2], (float)ei[E+j0+3]);
            m4 = make_float4(1.f, 1.f, 1.f, 1.f);
        } else {
            float* sp = &s4.x; float* dp = &d4.x; float* mp = &m4.x;
            #pragma unroll
            for (int t = 0; t < 4; t++) {
                int jp = j0 + t - E;          // synthetic index in [0, N*P)
                int node = jp / P;
                sp[t] = (float)node;
                dp[t] = (float)(N + jp);
                int deg = (int)rintf(pm[node]);  // jnp.round = half-to-even
                deg = max(0, min(deg, P));
                mp[t] = ((jp - node * P) < deg) ? 1.0f : 0.0f;
            }
        }
        int m4cnt = M / 4;                    // M is 4-aligned
        __stcs(&out[e_base4 + tid],             s4);
        __stcs(&out[e_base4 + m4cnt + tid],     d4);
        __stcs(&out[e_base4 + 2 * m4cnt + tid], m4);
    }
}

extern "C" void kernel_launch(void* const* d_in, const int* in_sizes, int n_in,
                              void* d_out, int out_size)
{
    const float* x   = (const float*)d_in[0];   // [N, F]
    const int*   ei  = (const int*)d_in[1];     // [2, E] int32
    const float* pm  = (const float*)d_in[2];   // [N]
    const float* gen = (const float*)d_in[3];   // [N, P*F]

    const int N   = in_sizes[2];
    const int E   = in_sizes[1] / 2;
    const int P   = in_sizes[3] / in_sizes[0];
    const int NFx = in_sizes[0];
    const int NFg = in_sizes[3];
    const int M   = E + N * P;

    const int nx4     = NFx / 4;
    const int total4  = (NFx + NFg) / 4;
    const int e_base4 = (NFx + NFg) / 4;
    const int edges4  = M / 4;

    const int threads = 256;
    int blocks = 148 * 8;                                  // persistent: 1 wave
    int min_blocks = (edges4 + threads - 1) / threads;     // enough threads for edges
    if (blocks < min_blocks) blocks = min_blocks;

    fused_kernel<<<blocks, threads>>>((const float4*)x, (const float4*)gen,
                                      ei, pm, (float4*)d_out,
                                      nx4, total4, e_base4, edges4,
                                      E, M, N, P);
}

// round 13
// speedup vs baseline: 1.0859x; 1.0859x over previous
#include <cuda_runtime.h>
#include <cuda_bf16.h>
#include <cstdint>

// MendGraph: fill_feats = [x; gen_feats], fill_edges = [edge_index | synthetic],
// edge_mask = [ones(E) | k < clip(round(pred_missing),0,P)].
//
// Output: 79,950,000 f32, flat concat (all cast to f32):
//   [0, NFx) x | [NFx, NFx+NFg) gen_feats | [B, B+M) src | [B+M, B+2M) dst | [B+2M, B+3M) mask
// B = NFx+NFg, M = E + N*P.  edge_index input is int32.
//
// FINAL (session best, R8/R11 config — measured optimum across 8 variants):
//  - Single fused kernel, flat multi-wave launch (37.5k CTAs x 256 thr).
//  - Uniform streaming copy: 2 block-strided float4 per thread; .cs
//    (evict-first) on BOTH loads and stores — measured best policy on B300
//    (default-wb stores +0.8us, persistent grid-stride +3.6us, both falsified).
//  - Edge/mask generation predicated onto the LAST M/4 threads so it lands in
//    the tail wave and hides fully under the 614MB feats copy.
// Measured: 88.6us kernel @ 6.52TB/s = sustained mixed R/W HBM ceiling (82% of
// spec); LTS 39%, issue 14%, occupancy slack — DRAM-floor bound.

__global__ void fused_kernel(const float4* __restrict__ x,
                             const float4* __restrict__ g,
                             const int*    __restrict__ ei,   // [2, E] int32
                             const float*  __restrict__ pm,   // [N]
                             float4* __restrict__ out,
                             int nx4, int total4,
                             int e_base4, int edges4,
                             int edge_tid0,                   // total_threads - edges4
                             int E, int M, int N, int P)
{
    // ---- streaming copy: 2 block-strided float4 groups per thread ----
    int k0 = blockIdx.x * (blockDim.x * 2) + threadIdx.x;
    int k1 = k0 + blockDim.x;

    float4 v0, v1;
    bool do0 = (k0 < total4), do1 = (k1 < total4);
    if (do0) v0 = (k0 < nx4) ? __ldcs(&x[k0]) : __ldcs(&g[k0 - nx4]);
    if (do1) v1 = (k1 < nx4) ? __ldcs(&x[k1]) : __ldcs(&g[k1 - nx4]);
    if (do0) __stcs(&out[k0], v0);
    if (do1) __stcs(&out[k1], v1);

    // ---- edges + mask: extra work for the LAST edges4 threads (tail wave) ----
    int tid = blockIdx.x * blockDim.x + threadIdx.x;
    int i   = tid - edge_tid0;
    if (i >= 0 && i < edges4) {
        int j0 = i * 4;
        float4 s4, d4, m4;
        if (j0 + 3 < E) {                    // E is 4-aligned: no straddle
            s4 = make_float4((float)ei[j0],   (float)ei[j0+1],
                             (float)ei[j0+2], (float)ei[j0+3]);
            d4 = make_float4((float)ei[E+j0],   (float)ei[E+j0+1],
                             (float)ei[E+j0+2], (float)ei[E+j0+3]);
            m4 = make_float4(1.f, 1.f, 1.f, 1.f);
        } else {
            float* sp = &s4.x; float* dp = &d4.x; float* mp = &m4.x;
            #pragma unroll
            for (int t = 0; t < 4; t++) {
                int jp = j0 + t - E;          // synthetic index in [0, N*P)
                int node = jp / P;
                sp[t] = (float)node;
                dp[t] = (float)(N + jp);
                int deg = (int)rintf(pm[node]);  // jnp.round = half-to-even
                deg = max(0, min(deg, P));
                mp[t] = ((jp - node * P) < deg) ? 1.0f : 0.0f;
            }
        }
        int m4cnt = M / 4;                    // M is 4-aligned
        __stcs(&out[e_base4 + i],             s4);
        __stcs(&out[e_base4 + m4cnt + i],     d4);
        __stcs(&out[e_base4 + 2 * m4cnt + i], m4);
    }
}

extern "C" void kernel_launch(void* const* d_in, const int* in_sizes, int n_in,
                              void* d_out, int out_size)
{
    const float* x   = (const float*)d_in[0];   // [N, F]
    const int*   ei  = (const int*)d_in[1];     // [2, E] int32
    const float* pm  = (const float*)d_in[2];   // [N]
    const float* gen = (const float*)d_in[3];   // [N, P*F]

    const int N   = in_sizes[2];
    const int E   = in_sizes[1] / 2;
    const int P   = in_sizes[3] / in_sizes[0];
    const int NFx = in_sizes[0];
    const int NFg = in_sizes[3];
    const int M   = E + N * P;

    const int nx4     = NFx / 4;
    const int total4  = (NFx + NFg) / 4;
    const int e_base4 = (NFx + NFg) / 4;
    const int edges4  = M / 4;

    const int threads = 256;
    const int per_blk = threads * 2;                       // 2 float4 per thread
    int blocks = (total4 + per_blk - 1) / per_blk;
    int min_blocks = (edges4 + threads - 1) / threads;     // enough threads for edges
    if (blocks < min_blocks) blocks = min_blocks;

    const int edge_tid0 = blocks * threads - edges4;       // last edges4 threads

    fused_kernel<<<blocks, threads>>>((const float4*)x, (const float4*)gen,
                                      ei, pm, (float4*)d_out,
                                      nx4, total4, e_base4, edges4, edge_tid0,
                                      E, M, N, P);
}